// round 12
// baseline (speedup 1.0000x reference)
#include <cuda_runtime.h>
#include <cstdint>
#include <cstddef>

// Problem constants
#define R_       64
#define S_       2048
#define K_       201
#define C_       512
#define PAD_LEN_ 2852
#define OUT_ONE_ 67108864ULL      // per-tensor output elems: S*H*F*R
#define NFULL_   12               // 12 full 16-tap chunks (taps 0..191)
#define NTAIL_   9                // tail chunk: taps 192..200 (201 total, zero waste)
#define NCHUNK_  13               // NFULL_ full chunks + 1 tail chunk

using ull = unsigned long long;

// Packed fp32x2 FMA (best fp32 path: 2 FMA / 3 cyc / SMSP at the RF-bank floor)
__device__ __forceinline__ void fma2(ull &acc, ull a, ull b) {
    asm("fma.rn.f32x2 %0, %1, %2, %0;" : "+l"(acc) : "l"(a), "l"(b));
}
__device__ __forceinline__ void mul2(ull &dst, ull a, ull b) {
    asm("mul.rn.f32x2 %0, %1, %2;" : "=l"(dst) : "l"(a), "l"(b));
}
__device__ __forceinline__ uint32_t sptr(const void* p) {
    return (uint32_t)__cvta_generic_to_shared(p);
}

// 0.125f in both packed halves (exact power of two -> bit-identical scaling)
#define EIGHTH2_ 0x3E0000003E000000ULL

// Weight stage: 4 buffers x [tensor][tap(16)][ch(64 floats)] = 4*2*16*64*4 = 32KB
// Epilogue transpose stage: 16*8*66*4 = 33792B (pad 66 keeps rows 8B-aligned
// for STS.64/LDS pairs). Union -> 33.8KB/block static; 2 blocks/SM.
struct __align__(16) SharedMem {
    union {
        float w[4][2][16][64];
        float stage[16][8][66];
    };
};

// Cooperative weight-chunk prefetch via cp.async. 8KB per chunk, 256 threads ->
// two 16B quads per thread. Taps >= K_ are zero-filled via src-size 0.
__device__ __forceinline__ void stage_weights(SharedMem& sh, int bufsel, int chunk,
                                              const float* __restrict__ w_k,
                                              const float* __restrict__ w_q,
                                              int cgbase, int tid) {
    #pragma unroll
    for (int h = 0; h < 2; ++h) {
        const int v      = h * 256 + tid;      // 0..511 quads
        const int tensor = v >> 8;             // 0 -> w_k (A), 1 -> w_q (B)
        const int tap    = (v >> 4) & 15;
        const int quad   = v & 15;             // 16 quads x 16B = 64 floats
        const int k      = chunk * 16 + tap;
        const int kc     = k < (K_ - 1) ? k : (K_ - 1);   // clamp addr, zfill via size
        const float* src = (tensor ? w_q : w_k) + (size_t)kc * C_ + cgbase + quad * 4;
        const uint32_t dst = sptr(&sh.w[bufsel][tensor][tap][quad * 4]);
        const int sz = (k < K_) ? 16 : 0;
        asm volatile("cp.async.ca.shared.global [%0], [%1], 16, %2;\n"
                     :: "r"(dst), "l"(src), "r"(sz));
    }
}

// NSTEP taps of the FIR: weights from smem, z from the register ring.
// Ring invariant: at step j, slot (i+j)&15 holds time base+j+i; refilling slot j
// at step j keeps the invariant for later steps. The tail chunk skips the refill
// on its final step. Two separate 16-FMA runs (all-A then all-B) per step.
template <int NSTEP, bool REFILL_LAST>
__device__ __forceinline__ void do_chunk(const float* __restrict__ wb, int lane,
                                         ull zr[16], ull aA[16], ull aB[16],
                                         const ull* __restrict__ zcur) {
    const ull* wp = (const ull*)wb + lane;     // tap row = 32 ull; tensor B at +512 ull
    #pragma unroll
    for (int j = 0; j < NSTEP; ++j) {
        const ull wA = wp[j * 32];
        const ull wB = wp[512 + j * 32];
        #pragma unroll
        for (int i = 0; i < 16; ++i) {
            fma2(aA[i], zr[(i + j) & 15], wA);
        }
        #pragma unroll
        for (int i = 0; i < 16; ++i) {
            fma2(aB[i], zr[(i + j) & 15], wB);
        }
        if (REFILL_LAST || j < NSTEP - 1) zr[j] = zcur[j * 256];
    }
}

// Block: 256 threads = 8 warps. warp w -> r = rg*8 + w; lane l -> channel pair
// cp = cg*64 + 2*l. Each thread: 16 consecutive t. Two blocks co-resident per SM
// with independent barriers/phases to cover each other's stalls.
//
// 4-buffer weight pipeline, ONE barrier per chunk:
//   iter i: stage(i+2) -> buf[(i+2)%4]; commit; wait_group<=2 (chunk i arrived);
//           BAR_i; compute(i) from buf[i%4].
// Safety: BAR_{i+1} implies all threads finished compute(i); the next write to
// buf[i%4] is stage(i+4) in iter i+2, which every thread reaches only after
// BAR_{i+1}. So no thread can overwrite a buffer another thread still reads.
__global__ __launch_bounds__(256, 2)
void conv_spe_kernel(const float* __restrict__ z,
                     const float* __restrict__ w_q,
                     const float* __restrict__ w_k,
                     float* __restrict__ out)
{
    __shared__ SharedMem sh;

    const int tid  = threadIdx.x;
    const int lane = tid & 31;
    const int rloc = tid >> 5;                 // warp = r-local
    const int r    = blockIdx.z * 8 + rloc;
    const int tt   = blockIdx.x * 16;          // block t-tile (=thread t base)
    const int cgb  = blockIdx.y * 64;
    const int cp   = cgb + lane * 2;

    const ull* zp = (const ull*)(z + (size_t)r * (PAD_LEN_ * C_) + cp);
    const int  zb = (tt + K_) * (C_ / 2);

    // Prologue: prefetch weight chunks 0 and 1 (separate commit groups)
    stage_weights(sh, 0, 0, w_k, w_q, cgb, tid);
    asm volatile("cp.async.commit_group;\n" ::: "memory");
    stage_weights(sh, 1, 1, w_k, w_q, cgb, tid);
    asm volatile("cp.async.commit_group;\n" ::: "memory");

    // Register ring: initially z[tt+K .. tt+K+15]
    ull zr[16];
    #pragma unroll
    for (int m = 0; m < 16; ++m) zr[m] = zp[zb + m * 256];

    ull aA[16], aB[16];    // A: conv w_k (tensor 0), B: conv w_q (tensor 1)
    #pragma unroll
    for (int i = 0; i < 16; ++i) { aA[i] = 0ULL; aB[i] = 0ULL; }

    const ull* zcur = zp + zb + 16 * 256;      // refill stream for chunk 0

    #pragma unroll 1
    for (int kb = 0; kb < NFULL_; ++kb) {
        if (kb + 2 < NCHUNK_) {
            stage_weights(sh, (kb + 2) & 3, kb + 2, w_k, w_q, cgb, tid);
            asm volatile("cp.async.commit_group;\n" ::: "memory");
            asm volatile("cp.async.wait_group 2;\n" ::: "memory");
        } else {
            asm volatile("cp.async.wait_group 0;\n" ::: "memory");
        }
        __syncthreads();                       // chunk kb staged for ALL threads
        do_chunk<16, true>(&sh.w[kb & 3][0][0][0], lane, zr, aA, aB, zcur);
        zcur += 16 * 256;
    }
    // Tail chunk (taps 192..200, 9 steps, buf (13-1)&3 = 0): refills at steps
    // 0..7; max refill z time = tt + K + 208 + 7 <= 2448 < 2852, in-bounds.
    asm volatile("cp.async.wait_group 0;\n" ::: "memory");
    __syncthreads();
    do_chunk<NTAIL_, false>(&sh.w[(NCHUNK_ - 1) & 3][0][0][0], lane, zr, aA, aB, zcur);
    __syncthreads();                           // weight buffers dead; stage reuse safe

    // ---- Epilogue: transpose through smem so stores are r-contiguous ----
    // out[s,h,f,r] = conv[r,t,c]/8 ; h=t>>8, f=(t>>2)&63, s=(t&3)*512+c
    #pragma unroll
    for (int sel = 0; sel < 2; ++sel) {
        const size_t obase = sel ? OUT_ONE_ : 0;
        __syncthreads();
        #pragma unroll
        for (int i = 0; i < 16; ++i) {
            ull v;
            mul2(v, sel == 0 ? aA[i] : aB[i], (ull)EIGHTH2_);
            *(ull*)&sh.stage[i][rloc][lane * 2] = v;   // 8B-aligned (row pad 66)
        }
        __syncthreads();
        // Each thread stores an r-adjacent float2 (r8 even -> 8B-aligned oidx);
        // warp covers 8-consecutive-r runs -> full 32B sectors.
        #pragma unroll
        for (int mm = 0; mm < 16; ++mm) {
            const int m  = mm * 512 + tid * 2; // even; 8192 floats total
            const int r8 = m & 7;              // 0,2,4,6
            const int cc = (m >> 3) & 63;
            const int ti = m >> 9;
            const int t  = tt + ti;
            const int c  = cgb + cc;
            const int sv = (t & 3) * 512 + c;
            const size_t oidx = obase
                              + (size_t)sv * 32768
                              + (size_t)((t >> 8) * 4096 + ((t >> 2) & 63) * 64)
                              + (size_t)(blockIdx.z * 8 + r8);
            float2 val;
            val.x = sh.stage[ti][r8][cc];
            val.y = sh.stage[ti][r8 + 1][cc];
            *(float2*)(out + oidx) = val;
        }
    }
}

extern "C" void kernel_launch(void* const* d_in, const int* in_sizes, int n_in,
                              void* d_out, int out_size) {
    const float* z   = (const float*)d_in[0];
    const float* w_q = (const float*)d_in[1];
    const float* w_k = (const float*)d_in[2];
    float* out = (float*)d_out;
    dim3 grid(128, 8, 8);   // (t_tiles of 16, ch_groups, r_groups)
    conv_spe_kernel<<<grid, 256>>>(z, w_q, w_k, out);
}

// round 13
// speedup vs baseline: 1.0346x; 1.0346x over previous
#include <cuda_runtime.h>
#include <cstdint>
#include <cstddef>

// Problem constants
#define R_       64
#define S_       2048
#define K_       201
#define C_       512
#define PAD_LEN_ 2852
#define OUT_ONE_ 67108864ULL      // per-tensor output elems: S*H*F*R
#define NFULL_   12               // 12 full 16-tap chunks (taps 0..191)
#define NTAIL_   9                // tail chunk: taps 192..200 (201 total, zero waste)
#define NCHUNK_  13               // NFULL_ full chunks + 1 tail chunk

using ull = unsigned long long;

// Packed fp32x2 FMA (best fp32 path: 2 FMA / 3 cyc / SMSP at the RF-bank floor)
__device__ __forceinline__ void fma2(ull &acc, ull a, ull b) {
    asm("fma.rn.f32x2 %0, %1, %2, %0;" : "+l"(acc) : "l"(a), "l"(b));
}
__device__ __forceinline__ float2 unpack2(ull v) {
    float2 f;
    asm("mov.b64 {%0, %1}, %2;" : "=f"(f.x), "=f"(f.y) : "l"(v));
    return f;
}
__device__ __forceinline__ uint32_t sptr(const void* p) {
    return (uint32_t)__cvta_generic_to_shared(p);
}

// Weight stage: 4 buffers x [tensor][tap(16)][ch(64 floats)] = 4*2*16*64*4 = 32KB
// Epilogue transpose stage: 16*8*65*4 = 33280B. Union -> 33.3KB/block; 2 blocks/SM.
struct __align__(16) SharedMem {
    union {
        float w[4][2][16][64];
        float stage[16][8][65];
    };
};

// Cooperative weight-chunk prefetch via cp.async. 8KB per chunk, 256 threads ->
// two 16B quads per thread. Taps >= K_ are zero-filled via src-size 0.
__device__ __forceinline__ void stage_weights(SharedMem& sh, int bufsel, int chunk,
                                              const float* __restrict__ w_k,
                                              const float* __restrict__ w_q,
                                              int cgbase, int tid) {
    #pragma unroll
    for (int h = 0; h < 2; ++h) {
        const int v      = h * 256 + tid;      // 0..511 quads
        const int tensor = v >> 8;             // 0 -> w_k (A), 1 -> w_q (B)
        const int tap    = (v >> 4) & 15;
        const int quad   = v & 15;             // 16 quads x 16B = 64 floats
        const int k      = chunk * 16 + tap;
        const int kc     = k < (K_ - 1) ? k : (K_ - 1);   // clamp addr, zfill via size
        const float* src = (tensor ? w_q : w_k) + (size_t)kc * C_ + cgbase + quad * 4;
        const uint32_t dst = sptr(&sh.w[bufsel][tensor][tap][quad * 4]);
        const int sz = (k < K_) ? 16 : 0;
        asm volatile("cp.async.ca.shared.global [%0], [%1], 16, %2;\n"
                     :: "r"(dst), "l"(src), "r"(sz));
    }
}

// NSTEP taps of the FIR: weights from smem, z from the register ring.
// Ring invariant: at step j, slot (i+j)&15 holds time base+j+i; refilling slot j
// at step j keeps the invariant for later steps. The tail chunk skips the refill
// on its final step. Two separate 16-FMA runs (all-A then all-B) per step.
template <int NSTEP, bool REFILL_LAST>
__device__ __forceinline__ void do_chunk(const float* __restrict__ wb, int lane,
                                         ull zr[16], ull aA[16], ull aB[16],
                                         const ull* __restrict__ zcur) {
    const ull* wp = (const ull*)wb + lane;     // tap row = 32 ull; tensor B at +512 ull
    #pragma unroll
    for (int j = 0; j < NSTEP; ++j) {
        const ull wA = wp[j * 32];
        const ull wB = wp[512 + j * 32];
        #pragma unroll
        for (int i = 0; i < 16; ++i) {
            fma2(aA[i], zr[(i + j) & 15], wA);
        }
        #pragma unroll
        for (int i = 0; i < 16; ++i) {
            fma2(aB[i], zr[(i + j) & 15], wB);
        }
        if (REFILL_LAST || j < NSTEP - 1) zr[j] = zcur[j * 256];
    }
}

// Block: 256 threads = 8 warps. warp w -> r = rg*8 + w; lane l -> channel pair
// cp = cg*64 + 2*l. Each thread: 16 consecutive t. Two blocks co-resident per SM
// with independent barriers/phases to cover each other's stalls.
//
// 4-buffer weight pipeline, ONE barrier per chunk:
//   iter i: stage(i+2) -> buf[(i+2)%4]; commit; wait_group<=2 (chunk i arrived);
//           BAR_i; compute(i) from buf[i%4].
// Safety: BAR_{i+1} implies all threads finished compute(i); the next write to
// buf[i%4] is stage(i+4) in iter i+2, which every thread reaches only after
// BAR_{i+1}. So no thread can overwrite a buffer another thread still reads.
__global__ __launch_bounds__(256, 2)
void conv_spe_kernel(const float* __restrict__ z,
                     const float* __restrict__ w_q,
                     const float* __restrict__ w_k,
                     float* __restrict__ out)
{
    __shared__ SharedMem sh;

    const int tid  = threadIdx.x;
    const int lane = tid & 31;
    const int rloc = tid >> 5;                 // warp = r-local
    const int r    = blockIdx.z * 8 + rloc;
    const int tt   = blockIdx.x * 16;          // block t-tile (=thread t base)
    const int cgb  = blockIdx.y * 64;
    const int cp   = cgb + lane * 2;

    const ull* zp = (const ull*)(z + (size_t)r * (PAD_LEN_ * C_) + cp);
    const int  zb = (tt + K_) * (C_ / 2);

    // Prologue: prefetch weight chunks 0 and 1 (separate commit groups)
    stage_weights(sh, 0, 0, w_k, w_q, cgb, tid);
    asm volatile("cp.async.commit_group;\n" ::: "memory");
    stage_weights(sh, 1, 1, w_k, w_q, cgb, tid);
    asm volatile("cp.async.commit_group;\n" ::: "memory");

    // Register ring: initially z[tt+K .. tt+K+15]
    ull zr[16];
    #pragma unroll
    for (int m = 0; m < 16; ++m) zr[m] = zp[zb + m * 256];

    ull aA[16], aB[16];    // A: conv w_k (tensor 0), B: conv w_q (tensor 1)
    #pragma unroll
    for (int i = 0; i < 16; ++i) { aA[i] = 0ULL; aB[i] = 0ULL; }

    const ull* zcur = zp + zb + 16 * 256;      // refill stream for chunk 0

    #pragma unroll 1
    for (int kb = 0; kb < NFULL_; ++kb) {
        if (kb + 2 < NCHUNK_) {
            stage_weights(sh, (kb + 2) & 3, kb + 2, w_k, w_q, cgb, tid);
            asm volatile("cp.async.commit_group;\n" ::: "memory");
            asm volatile("cp.async.wait_group 2;\n" ::: "memory");
        } else {
            asm volatile("cp.async.wait_group 0;\n" ::: "memory");
        }
        __syncthreads();                       // chunk kb staged for ALL threads
        do_chunk<16, true>(&sh.w[kb & 3][0][0][0], lane, zr, aA, aB, zcur);
        zcur += 16 * 256;
    }
    // Tail chunk (taps 192..200, 9 steps, buf (13-1)&3 = 0): refills at steps
    // 0..7; max refill z time = tt + K + 208 + 7 <= 2448 < 2852, in-bounds.
    asm volatile("cp.async.wait_group 0;\n" ::: "memory");
    __syncthreads();
    do_chunk<NTAIL_, false>(&sh.w[(NCHUNK_ - 1) & 3][0][0][0], lane, zr, aA, aB, zcur);
    __syncthreads();                           // weight buffers dead; stage reuse safe

    // ---- Epilogue: transpose through smem so stores are r-contiguous ----
    // out[s,h,f,r] = conv[r,t,c]/8 ; h=t>>8, f=(t>>2)&63, s=(t&3)*512+c
    #pragma unroll
    for (int sel = 0; sel < 2; ++sel) {
        const size_t obase = sel ? OUT_ONE_ : 0;
        __syncthreads();
        #pragma unroll
        for (int i = 0; i < 16; ++i) {
            const float2 f = unpack2(sel == 0 ? aA[i] : aB[i]);
            sh.stage[i][rloc][lane * 2]     = f.x * 0.125f;
            sh.stage[i][rloc][lane * 2 + 1] = f.y * 0.125f;
        }
        __syncthreads();
        #pragma unroll
        for (int mm = 0; mm < 32; ++mm) {
            const int m  = mm * 256 + tid;     // 8192 floats
            const int r8 = m & 7;
            const int cc = (m >> 3) & 63;
            const int ti = m >> 9;
            const int t  = tt + ti;
            const int c  = cgb + cc;
            const int sv = (t & 3) * 512 + c;
            const size_t oidx = obase
                              + (size_t)sv * 32768
                              + (size_t)((t >> 8) * 4096 + ((t >> 2) & 63) * 64)
                              + (size_t)(blockIdx.z * 8 + r8);
            out[oidx] = sh.stage[ti][r8][cc];
        }
    }
}

extern "C" void kernel_launch(void* const* d_in, const int* in_sizes, int n_in,
                              void* d_out, int out_size) {
    const float* z   = (const float*)d_in[0];
    const float* w_q = (const float*)d_in[1];
    const float* w_k = (const float*)d_in[2];
    float* out = (float*)d_out;
    dim3 grid(128, 8, 8);   // (t_tiles of 16, ch_groups, r_groups)
    conv_spe_kernel<<<grid, 256>>>(z, w_q, w_k, out);
}